// round 10
// baseline (speedup 1.0000x reference)
#include <cuda_runtime.h>
#include <cuda_bf16.h>

// Problem constants (fixed by the dataset)
#define NNODES 100000
#define NEDGES 1600000
#define DFEAT  64
#define NGRAPH 64
#define SLOT   64      // max in-degree slots per node (Poisson(16) -> P(overflow) ~ 1e-14)

// ---------------- constant memory for weights ----------------
__constant__ float cW1[DFEAT * DFEAT];
__constant__ float cW2[DFEAT * DFEAT];
__constant__ float cW3[DFEAT * DFEAT];

// ---------------- device scratch (no allocations allowed) ----------------
__device__ int   g_cnt  [NNODES];          // in-degree (edges only, excl. self loop)
__device__ int   g_slots[NNODES * SLOT];   // per-dst list of src node ids
__device__ float g_dis  [NNODES];
__device__ float g_hs   [NNODES * DFEAT];  // (x @ W) * dis[row]
__device__ float g_x1   [NNODES * DFEAT];  // layer output ping
__device__ float g_x2   [NNODES * DFEAT];  // layer output pong

// ---------------- kernels ----------------

// cnt = 0; out[g] = lin_b
__global__ void init_kernel(float* __restrict__ out, const float* __restrict__ lin_b) {
    int i = blockIdx.x * blockDim.x + threadIdx.x;
    if (i < NNODES) g_cnt[i] = 0;
    if (i < NGRAPH) out[i] = lin_b[0];
}

// bucket-build: slots[dst][pos++] = src
__global__ void build_kernel(const int* __restrict__ src, const int* __restrict__ dst) {
    int e = blockIdx.x * blockDim.x + threadIdx.x;
    if (e >= NEDGES) return;
    int d = __ldg(&dst[e]);
    int s = __ldg(&src[e]);
    int pos = atomicAdd(&g_cnt[d], 1);
    if (pos < SLOT) g_slots[d * SLOT + pos] = s;
}

// dis = rsqrt(1 + cnt)   (self loop contributes 1)
__global__ void dis_kernel() {
    int i = blockIdx.x * blockDim.x + threadIdx.x;
    if (i < NNODES) g_dis[i] = rsqrtf(1.0f + (float)g_cnt[i]);
}

// Compile-time selection of the constant weight array (keeps LDC/LDCU, avoids
// generic-pointer loads).
template <int L>
__device__ __forceinline__ float4 ldW4(int idx) {
    if constexpr (L == 0) return *reinterpret_cast<const float4*>(cW1 + idx);
    else if constexpr (L == 1) return *reinterpret_cast<const float4*>(cW2 + idx);
    else return *reinterpret_cast<const float4*>(cW3 + idx);
}

// hs[row] = (x[row] @ W) * dis[row]
// grid = (ceil(N/512), 2): each block covers 512 rows with 256 threads
// (2 rows per thread -> each constant W load feeds 8 FMAs, halving the
// constant-port load). blockIdx.y selects the 32-column half; it is uniform
// by construction so W addresses stay (immediate + uniform) -> const port.
template <int L>
__global__ __launch_bounds__(256) void gemm_scale_kernel(
    const float* __restrict__ x, float* __restrict__ hs)
{
    int row0 = blockIdx.x * 512 + threadIdx.x;
    int row1 = row0 + 256;
    if (row0 >= NNODES) return;
    bool v1 = (row1 < NNODES);
    const int hoff = blockIdx.y * 32;     // uniform constant offset

    float a0[32], a1[32];
    #pragma unroll
    for (int j = 0; j < 32; j++) { a0[j] = 0.0f; a1[j] = 0.0f; }

    const float4* xr0 = reinterpret_cast<const float4*>(x + (size_t)row0 * DFEAT);
    const float4* xr1 = reinterpret_cast<const float4*>(x + (size_t)(v1 ? row1 : row0) * DFEAT);

    #pragma unroll
    for (int kk = 0; kk < 16; kk++) {
        float4 xv0 = __ldg(&xr0[kk]);
        float4 xv1 = __ldg(&xr1[kk]);
        #pragma unroll
        for (int u = 0; u < 4; u++) {
            float xs0 = (u == 0) ? xv0.x : (u == 1) ? xv0.y : (u == 2) ? xv0.z : xv0.w;
            float xs1 = (u == 0) ? xv1.x : (u == 1) ? xv1.y : (u == 2) ? xv1.z : xv1.w;
            const int base = (kk * 4 + u) * DFEAT + hoff;
            #pragma unroll
            for (int jq = 0; jq < 8; jq++) {
                float4 w4 = ldW4<L>(base + jq * 4);
                a0[jq * 4 + 0] = fmaf(xs0, w4.x, a0[jq * 4 + 0]);
                a0[jq * 4 + 1] = fmaf(xs0, w4.y, a0[jq * 4 + 1]);
                a0[jq * 4 + 2] = fmaf(xs0, w4.z, a0[jq * 4 + 2]);
                a0[jq * 4 + 3] = fmaf(xs0, w4.w, a0[jq * 4 + 3]);
                a1[jq * 4 + 0] = fmaf(xs1, w4.x, a1[jq * 4 + 0]);
                a1[jq * 4 + 1] = fmaf(xs1, w4.y, a1[jq * 4 + 1]);
                a1[jq * 4 + 2] = fmaf(xs1, w4.z, a1[jq * 4 + 2]);
                a1[jq * 4 + 3] = fmaf(xs1, w4.w, a1[jq * 4 + 3]);
            }
        }
    }

    float dr0 = g_dis[row0];
    float4* h0 = reinterpret_cast<float4*>(hs + (size_t)row0 * DFEAT + hoff);
    #pragma unroll
    for (int jq = 0; jq < 8; jq++)
        h0[jq] = make_float4(a0[jq*4+0]*dr0, a0[jq*4+1]*dr0, a0[jq*4+2]*dr0, a0[jq*4+3]*dr0);

    if (v1) {
        float dr1 = g_dis[row1];
        float4* h1 = reinterpret_cast<float4*>(hs + (size_t)row1 * DFEAT + hoff);
        #pragma unroll
        for (int jq = 0; jq < 8; jq++)
            h1[jq] = make_float4(a1[jq*4+0]*dr1, a1[jq*4+1]*dr1, a1[jq*4+2]*dr1, a1[jq*4+3]*dr1);
    }
}

// Gather-aggregate + finalize: 16 threads per node (one float4 column chunk each).
//   s = hs[n] + sum_{k<cnt[n]} hs[slots[n][k]]
//   o = relu(dis[n] * s + b)
// DO_READOUT: instead of writing o, accumulate dot(o, lin_w) into out[batch[n]].
template <bool DO_READOUT>
__global__ void aggregate_kernel(const float4* __restrict__ hs,
                                 const float*  __restrict__ b,
                                 float4* __restrict__ xout,
                                 const int*   __restrict__ batch,
                                 const float* __restrict__ lin_w,
                                 float* __restrict__ out)
{
    __shared__ float bins[NGRAPH];
    if (DO_READOUT) {
        if (threadIdx.x < NGRAPH) bins[threadIdx.x] = 0.0f;
        __syncthreads();
    }

    int t = blockIdx.x * blockDim.x + threadIdx.x;
    int n = t >> 4;
    int c = t & 15;
    if (n < NNODES) {
        const int* sl = &g_slots[(size_t)n * SLOT];
        int cnt = g_cnt[n];

        float4 s = __ldg(&hs[n * 16 + c]);   // self loop
        int k = 0;
        for (; k + 1 < cnt; k += 2) {        // unroll-2 for MLP
            int s0 = __ldg(&sl[k]);
            int s1 = __ldg(&sl[k + 1]);
            float4 v0 = __ldg(&hs[s0 * 16 + c]);
            float4 v1 = __ldg(&hs[s1 * 16 + c]);
            s.x += v0.x + v1.x; s.y += v0.y + v1.y;
            s.z += v0.z + v1.z; s.w += v0.w + v1.w;
        }
        if (k < cnt) {
            int s0 = __ldg(&sl[k]);
            float4 v0 = __ldg(&hs[s0 * 16 + c]);
            s.x += v0.x; s.y += v0.y; s.z += v0.z; s.w += v0.w;
        }

        float dr = g_dis[n];
        float4 bb = *reinterpret_cast<const float4*>(&b[c * 4]);
        float4 o;
        o.x = fmaxf(fmaf(dr, s.x, bb.x), 0.0f);
        o.y = fmaxf(fmaf(dr, s.y, bb.y), 0.0f);
        o.z = fmaxf(fmaf(dr, s.z, bb.z), 0.0f);
        o.w = fmaxf(fmaf(dr, s.w, bb.w), 0.0f);

        if (!DO_READOUT) {
            xout[n * 16 + c] = o;
        } else {
            float4 lw = *reinterpret_cast<const float4*>(&lin_w[c * 4]);
            float d = o.x * lw.x + o.y * lw.y + o.z * lw.z + o.w * lw.w;
            // reduce across the 16-lane group
            #pragma unroll
            for (int off = 8; off >= 1; off >>= 1)
                d += __shfl_down_sync(0xFFFFFFFFu, d, off, 16);
            if (c == 0) atomicAdd(&bins[__ldg(&batch[n])], d);
        }
    }

    if (DO_READOUT) {
        __syncthreads();
        if (threadIdx.x < NGRAPH && bins[threadIdx.x] != 0.0f)
            atomicAdd(&out[threadIdx.x], bins[threadIdx.x]);
    }
}

// ---------------- launch ----------------
extern "C" void kernel_launch(void* const* d_in, const int* in_sizes, int n_in,
                              void* d_out, int out_size)
{
    const float* x     = (const float*)d_in[0];
    const int*   eidx  = (const int*)  d_in[1];   // [2, E]: row 0 = src, row 1 = dst
    const int*   batch = (const int*)  d_in[2];
    const float* W1    = (const float*)d_in[3];
    const float* b1    = (const float*)d_in[4];
    const float* W2    = (const float*)d_in[5];
    const float* b2    = (const float*)d_in[6];
    const float* W3    = (const float*)d_in[7];
    const float* b3    = (const float*)d_in[8];
    const float* lin_w = (const float*)d_in[9];
    const float* lin_b = (const float*)d_in[10];
    float* out = (float*)d_out;

    const int* src = eidx;
    const int* dst = eidx + NEDGES;

    float *hs, *x1, *x2;
    cudaGetSymbolAddress((void**)&hs, g_hs);
    cudaGetSymbolAddress((void**)&x1, g_x1);
    cudaGetSymbolAddress((void**)&x2, g_x2);

    // Stage weights into constant memory (plain D2D async copies; allowed
    // under graph capture).
    void *pW1, *pW2, *pW3;
    cudaGetSymbolAddress(&pW1, cW1);
    cudaGetSymbolAddress(&pW2, cW2);
    cudaGetSymbolAddress(&pW3, cW3);
    cudaMemcpyAsync(pW1, W1, DFEAT * DFEAT * sizeof(float),
                    cudaMemcpyDeviceToDevice, 0);
    cudaMemcpyAsync(pW2, W2, DFEAT * DFEAT * sizeof(float),
                    cudaMemcpyDeviceToDevice, 0);
    cudaMemcpyAsync(pW3, W3, DFEAT * DFEAT * sizeof(float),
                    cudaMemcpyDeviceToDevice, 0);

    const int TB = 256;
    dim3 gN((NNODES + TB - 1) / TB);
    dim3 gE((NEDGES + TB - 1) / TB);
    dim3 gN16((NNODES * 16 + TB - 1) / TB);
    dim3 gG((NNODES + 511) / 512, 2);   // gemm: 512 rows/block (2/thread), y = column half

    // degree buckets + norm
    init_kernel<<<gN, TB>>>(out, lin_b);
    build_kernel<<<gE, TB>>>(src, dst);
    dis_kernel<<<gN, TB>>>();

    // layer 1: x -> x1
    gemm_scale_kernel<0><<<gG, 256>>>(x, hs);
    aggregate_kernel<false><<<gN16, TB>>>((const float4*)hs, b1, (float4*)x1,
                                          nullptr, nullptr, nullptr);
    // layer 2: x1 -> x2
    gemm_scale_kernel<1><<<gG, 256>>>(x1, hs);
    aggregate_kernel<false><<<gN16, TB>>>((const float4*)hs, b2, (float4*)x2,
                                          nullptr, nullptr, nullptr);
    // layer 3: x2 -> (fused pool + linear head)
    gemm_scale_kernel<2><<<gG, 256>>>(x2, hs);
    aggregate_kernel<true><<<gN16, TB>>>((const float4*)hs, b3, nullptr,
                                         batch, lin_w, out);
}

// round 14
// speedup vs baseline: 1.2004x; 1.2004x over previous
#include <cuda_runtime.h>
#include <cuda_fp16.h>

// Problem constants (fixed by the dataset)
#define NNODES 100000
#define NEDGES 1600000
#define DFEAT  64
#define NGRAPH 64
#define SLOT   64      // max in-degree slots per node (Poisson(16) -> P(overflow) ~ 1e-14)

// ---------------- constant memory for weights ----------------
__constant__ float cW1[DFEAT * DFEAT];
__constant__ float cW2[DFEAT * DFEAT];
__constant__ float cW3[DFEAT * DFEAT];

// ---------------- device scratch (no allocations allowed) ----------------
__device__ int    g_cnt  [NNODES];          // in-degree (edges only, excl. self loop)
__device__ int    g_slots[NNODES * SLOT];   // per-dst list of src node ids
__device__ float  g_dis  [NNODES];
__device__ __half g_hs   [NNODES * DFEAT];  // (x @ W) * dis[row], fp16 payload
__device__ float  g_x1   [NNODES * DFEAT];  // layer output ping (fp32)
__device__ float  g_x2   [NNODES * DFEAT];  // layer output pong (fp32)

// ---------------- kernels ----------------

// cnt = 0; out[g] = lin_b
__global__ void init_kernel(float* __restrict__ out, const float* __restrict__ lin_b) {
    int i = blockIdx.x * blockDim.x + threadIdx.x;
    if (i < NNODES) g_cnt[i] = 0;
    if (i < NGRAPH) out[i] = lin_b[0];
}

// bucket-build: slots[dst][pos++] = src
__global__ void build_kernel(const int* __restrict__ src, const int* __restrict__ dst) {
    int e = blockIdx.x * blockDim.x + threadIdx.x;
    if (e >= NEDGES) return;
    int d = __ldg(&dst[e]);
    int s = __ldg(&src[e]);
    int pos = atomicAdd(&g_cnt[d], 1);
    if (pos < SLOT) g_slots[d * SLOT + pos] = s;
}

// dis = rsqrt(1 + cnt)   (self loop contributes 1)
__global__ void dis_kernel() {
    int i = blockIdx.x * blockDim.x + threadIdx.x;
    if (i < NNODES) g_dis[i] = rsqrtf(1.0f + (float)g_cnt[i]);
}

// Compile-time selection of the constant weight array (keeps LDC/LDCU, avoids
// generic-pointer loads).
template <int L>
__device__ __forceinline__ float4 ldW4(int idx) {
    if constexpr (L == 0) return *reinterpret_cast<const float4*>(cW1 + idx);
    else if constexpr (L == 1) return *reinterpret_cast<const float4*>(cW2 + idx);
    else return *reinterpret_cast<const float4*>(cW3 + idx);
}

// hs[row] = fp16( (x[row] @ W) * dis[row] )
// R9 config (best measured): 1 row/thread, 256 threads, grid.y = column half.
// blockIdx.y is uniform -> W addresses are (immediate + uniform) -> const port.
template <int L>
__global__ __launch_bounds__(256) void gemm_scale_kernel(
    const float* __restrict__ x, __half* __restrict__ hs)
{
    int row = blockIdx.x * 256 + threadIdx.x;
    if (row >= NNODES) return;
    const int hoff = blockIdx.y * 32;     // uniform column offset (in elements)

    float a[32];
    #pragma unroll
    for (int j = 0; j < 32; j++) a[j] = 0.0f;

    const float4* xr = reinterpret_cast<const float4*>(x + (size_t)row * DFEAT);
    #pragma unroll
    for (int kk = 0; kk < 16; kk++) {
        float4 xv = __ldg(&xr[kk]);
        #pragma unroll
        for (int u = 0; u < 4; u++) {
            float xs = (u == 0) ? xv.x : (u == 1) ? xv.y : (u == 2) ? xv.z : xv.w;
            const int base = (kk * 4 + u) * DFEAT + hoff;
            #pragma unroll
            for (int jq = 0; jq < 8; jq++) {
                float4 w4 = ldW4<L>(base + jq * 4);
                a[jq * 4 + 0] = fmaf(xs, w4.x, a[jq * 4 + 0]);
                a[jq * 4 + 1] = fmaf(xs, w4.y, a[jq * 4 + 1]);
                a[jq * 4 + 2] = fmaf(xs, w4.z, a[jq * 4 + 2]);
                a[jq * 4 + 3] = fmaf(xs, w4.w, a[jq * 4 + 3]);
            }
        }
    }

    float dr = g_dis[row];
    // pack 32 fp32 results -> 32 halves = 4 x uint4 stores
    uint4* ho = reinterpret_cast<uint4*>(hs + (size_t)row * DFEAT + hoff);
    #pragma unroll
    for (int q = 0; q < 4; q++) {
        __half2 p[4];
        #pragma unroll
        for (int i = 0; i < 4; i++)
            p[i] = __floats2half2_rn(a[q * 8 + i * 2] * dr, a[q * 8 + i * 2 + 1] * dr);
        ho[q] = *reinterpret_cast<uint4*>(p);
    }
}

// Gather-aggregate + finalize: 8 threads per node (one uint4 = 8 halves each).
//   s = hs[n] + sum_{k<cnt[n]} hs[slots[n][k]]   (fp32 accumulation)
//   o = relu(dis[n] * s + b)
// DO_READOUT: instead of writing o, accumulate dot(o, lin_w) into out[batch[n]].
template <bool DO_READOUT>
__global__ void aggregate_kernel(const __half* __restrict__ hs,
                                 const float*  __restrict__ b,
                                 float* __restrict__ xout,
                                 const int*   __restrict__ batch,
                                 const float* __restrict__ lin_w,
                                 float* __restrict__ out)
{
    __shared__ float bins[NGRAPH];
    if (DO_READOUT) {
        if (threadIdx.x < NGRAPH) bins[threadIdx.x] = 0.0f;
        __syncthreads();
    }

    int t = blockIdx.x * blockDim.x + threadIdx.x;
    int n = t >> 3;
    int c = t & 7;
    if (n < NNODES) {
        const uint4* hv = reinterpret_cast<const uint4*>(hs);   // 8 halves / uint4
        const int* sl = &g_slots[(size_t)n * SLOT];
        int cnt = g_cnt[n];

        float acc[8];
        {   // self loop
            uint4 r = __ldg(&hv[n * 8 + c]);
            const __half2* h = reinterpret_cast<const __half2*>(&r);
            #pragma unroll
            for (int i = 0; i < 4; i++) {
                float2 f = __half22float2(h[i]);
                acc[i * 2] = f.x; acc[i * 2 + 1] = f.y;
            }
        }
        int k = 0;
        for (; k + 1 < cnt; k += 2) {        // unroll-2 for MLP
            int s0 = __ldg(&sl[k]);
            int s1 = __ldg(&sl[k + 1]);
            uint4 r0 = __ldg(&hv[s0 * 8 + c]);
            uint4 r1 = __ldg(&hv[s1 * 8 + c]);
            const __half2* h0 = reinterpret_cast<const __half2*>(&r0);
            const __half2* h1 = reinterpret_cast<const __half2*>(&r1);
            #pragma unroll
            for (int i = 0; i < 4; i++) {
                float2 f0 = __half22float2(h0[i]);
                float2 f1 = __half22float2(h1[i]);
                acc[i * 2]     += f0.x + f1.x;
                acc[i * 2 + 1] += f0.y + f1.y;
            }
        }
        if (k < cnt) {
            int s0 = __ldg(&sl[k]);
            uint4 r0 = __ldg(&hv[s0 * 8 + c]);
            const __half2* h0 = reinterpret_cast<const __half2*>(&r0);
            #pragma unroll
            for (int i = 0; i < 4; i++) {
                float2 f0 = __half22float2(h0[i]);
                acc[i * 2] += f0.x; acc[i * 2 + 1] += f0.y;
            }
        }

        float dr = g_dis[n];
        const float4* bb = reinterpret_cast<const float4*>(&b[c * 8]);
        float4 b0 = __ldg(&bb[0]);
        float4 b1 = __ldg(&bb[1]);
        float o[8];
        o[0] = fmaxf(fmaf(dr, acc[0], b0.x), 0.0f);
        o[1] = fmaxf(fmaf(dr, acc[1], b0.y), 0.0f);
        o[2] = fmaxf(fmaf(dr, acc[2], b0.z), 0.0f);
        o[3] = fmaxf(fmaf(dr, acc[3], b0.w), 0.0f);
        o[4] = fmaxf(fmaf(dr, acc[4], b1.x), 0.0f);
        o[5] = fmaxf(fmaf(dr, acc[5], b1.y), 0.0f);
        o[6] = fmaxf(fmaf(dr, acc[6], b1.z), 0.0f);
        o[7] = fmaxf(fmaf(dr, acc[7], b1.w), 0.0f);

        if (!DO_READOUT) {
            float4* xo = reinterpret_cast<float4*>(xout + (size_t)n * DFEAT + c * 8);
            xo[0] = make_float4(o[0], o[1], o[2], o[3]);
            xo[1] = make_float4(o[4], o[5], o[6], o[7]);
        } else {
            const float4* lwv = reinterpret_cast<const float4*>(&lin_w[c * 8]);
            float4 l0 = __ldg(&lwv[0]);
            float4 l1 = __ldg(&lwv[1]);
            float d = o[0]*l0.x + o[1]*l0.y + o[2]*l0.z + o[3]*l0.w
                    + o[4]*l1.x + o[5]*l1.y + o[6]*l1.z + o[7]*l1.w;
            // reduce across the 8-lane group
            #pragma unroll
            for (int off = 4; off >= 1; off >>= 1)
                d += __shfl_down_sync(0xFFFFFFFFu, d, off, 8);
            if (c == 0) atomicAdd(&bins[__ldg(&batch[n])], d);
        }
    }

    if (DO_READOUT) {
        __syncthreads();
        if (threadIdx.x < NGRAPH && bins[threadIdx.x] != 0.0f)
            atomicAdd(&out[threadIdx.x], bins[threadIdx.x]);
    }
}

// ---------------- launch ----------------
extern "C" void kernel_launch(void* const* d_in, const int* in_sizes, int n_in,
                              void* d_out, int out_size)
{
    const float* x     = (const float*)d_in[0];
    const int*   eidx  = (const int*)  d_in[1];   // [2, E]: row 0 = src, row 1 = dst
    const int*   batch = (const int*)  d_in[2];
    const float* W1    = (const float*)d_in[3];
    const float* b1    = (const float*)d_in[4];
    const float* W2    = (const float*)d_in[5];
    const float* b2    = (const float*)d_in[6];
    const float* W3    = (const float*)d_in[7];
    const float* b3    = (const float*)d_in[8];
    const float* lin_w = (const float*)d_in[9];
    const float* lin_b = (const float*)d_in[10];
    float* out = (float*)d_out;

    const int* src = eidx;
    const int* dst = eidx + NEDGES;

    __half* hs;
    float *x1, *x2;
    cudaGetSymbolAddress((void**)&hs, g_hs);
    cudaGetSymbolAddress((void**)&x1, g_x1);
    cudaGetSymbolAddress((void**)&x2, g_x2);

    // Stage weights into constant memory (plain D2D async copies; allowed
    // under graph capture).
    void *pW1, *pW2, *pW3;
    cudaGetSymbolAddress(&pW1, cW1);
    cudaGetSymbolAddress(&pW2, cW2);
    cudaGetSymbolAddress(&pW3, cW3);
    cudaMemcpyAsync(pW1, W1, DFEAT * DFEAT * sizeof(float),
                    cudaMemcpyDeviceToDevice, 0);
    cudaMemcpyAsync(pW2, W2, DFEAT * DFEAT * sizeof(float),
                    cudaMemcpyDeviceToDevice, 0);
    cudaMemcpyAsync(pW3, W3, DFEAT * DFEAT * sizeof(float),
                    cudaMemcpyDeviceToDevice, 0);

    const int TB = 256;
    dim3 gN((NNODES + TB - 1) / TB);
    dim3 gE((NEDGES + TB - 1) / TB);
    dim3 gN8((NNODES * 8 + TB - 1) / TB);
    dim3 gG((NNODES + 255) / 256, 2);   // gemm: 256 rows/block, y = column half

    // degree buckets + norm
    init_kernel<<<gN, TB>>>(out, lin_b);
    build_kernel<<<gE, TB>>>(src, dst);
    dis_kernel<<<gN, TB>>>();

    // layer 1: x -> x1
    gemm_scale_kernel<0><<<gG, 256>>>(x, hs);
    aggregate_kernel<false><<<gN8, TB>>>(hs, b1, x1, nullptr, nullptr, nullptr);
    // layer 2: x1 -> x2
    gemm_scale_kernel<1><<<gG, 256>>>(x1, hs);
    aggregate_kernel<false><<<gN8, TB>>>(hs, b2, x2, nullptr, nullptr, nullptr);
    // layer 3: x2 -> (fused pool + linear head)
    gemm_scale_kernel<2><<<gG, 256>>>(x2, hs);
    aggregate_kernel<true><<<gN8, TB>>>(hs, b3, nullptr, batch, lin_w, out);
}

// round 16
// speedup vs baseline: 1.2907x; 1.0752x over previous
#include <cuda_runtime.h>
#include <cuda_fp16.h>

// Problem constants (fixed by the dataset)
#define NNODES 100000
#define NEDGES 1600000
#define DFEAT  64
#define NGRAPH 64
#define SLOT   64      // max in-degree slots per node (Poisson(16) -> P(overflow) ~ 1e-14)

// ---------------- constant memory for weights ----------------
__constant__ float cW1[DFEAT * DFEAT];
__constant__ float cW2[DFEAT * DFEAT];
__constant__ float cW3[DFEAT * DFEAT];

// ---------------- device scratch (no allocations allowed) ----------------
__device__ int    g_cnt  [NNODES];          // in-degree (edges only, excl. self loop)
__device__ int    g_slots[NNODES * SLOT];   // per-dst list of src node ids
__device__ float  g_dis  [NNODES];
__device__ __half g_hs   [NNODES * DFEAT];  // (x @ W) * dis[row], fp16 payload
__device__ float  g_x1   [NNODES * DFEAT];  // layer output ping (fp32)
__device__ float  g_x2   [NNODES * DFEAT];  // layer output pong (fp32)

// ---------------- packed f32x2 helpers (Blackwell FFMA2) ----------------
__device__ __forceinline__ void ffma2(unsigned long long& acc,
                                      unsigned long long w2,
                                      unsigned long long x2) {
    asm("fma.rn.f32x2 %0, %1, %2, %0;" : "+l"(acc) : "l"(w2), "l"(x2));
}
__device__ __forceinline__ unsigned long long pack2(float v) {
    unsigned long long r;
    asm("mov.b64 %0, {%1, %1};" : "=l"(r) : "f"(v));
    return r;
}
__device__ __forceinline__ float2 unpack2(unsigned long long v) {
    float lo, hi;
    asm("mov.b64 {%0, %1}, %2;" : "=f"(lo), "=f"(hi) : "l"(v));
    return make_float2(lo, hi);
}

// ---------------- kernels ----------------

// cnt = 0; out[g] = lin_b
__global__ void init_kernel(float* __restrict__ out, const float* __restrict__ lin_b) {
    int i = blockIdx.x * blockDim.x + threadIdx.x;
    if (i < NNODES) g_cnt[i] = 0;
    if (i < NGRAPH) out[i] = lin_b[0];
}

// bucket-build: slots[dst][pos++] = src
__global__ void build_kernel(const int* __restrict__ src, const int* __restrict__ dst) {
    int e = blockIdx.x * blockDim.x + threadIdx.x;
    if (e >= NEDGES) return;
    int d = __ldg(&dst[e]);
    int s = __ldg(&src[e]);
    int pos = atomicAdd(&g_cnt[d], 1);
    if (pos < SLOT) g_slots[d * SLOT + pos] = s;
}

// dis = rsqrt(1 + cnt)   (self loop contributes 1)
__global__ void dis_kernel() {
    int i = blockIdx.x * blockDim.x + threadIdx.x;
    if (i < NNODES) g_dis[i] = rsqrtf(1.0f + (float)g_cnt[i]);
}

// Compile-time selection of the constant weight array (keeps LDC, avoids
// generic-pointer loads). Returns 2 packed f32x2 pairs (one LDC.128).
template <int L>
__device__ __forceinline__ ulonglong2 ldW2x2(int idx) {
    if constexpr (L == 0) return *reinterpret_cast<const ulonglong2*>(cW1 + idx);
    else if constexpr (L == 1) return *reinterpret_cast<const ulonglong2*>(cW2 + idx);
    else return *reinterpret_cast<const ulonglong2*>(cW3 + idx);
}

// hs[row] = fp16( (x[row] @ W) * dis[row] )
// 1 row/thread, 256 threads, grid.y = column half (uniform const offsets).
// Inner product uses packed fma.rn.f32x2 (FFMA2): 2 MACs per instruction.
template <int L>
__global__ __launch_bounds__(256) void gemm_scale_kernel(
    const float* __restrict__ x, __half* __restrict__ hs)
{
    int row = blockIdx.x * 256 + threadIdx.x;
    if (row >= NNODES) return;
    const int hoff = blockIdx.y * 32;     // uniform column offset (in elements)

    unsigned long long a[16];             // 16 packed f32x2 accumulators = 32 cols
    #pragma unroll
    for (int j = 0; j < 16; j++) a[j] = 0ull;

    const float4* xr = reinterpret_cast<const float4*>(x + (size_t)row * DFEAT);
    #pragma unroll
    for (int kk = 0; kk < 16; kk++) {
        float4 xv = __ldg(&xr[kk]);
        #pragma unroll
        for (int u = 0; u < 4; u++) {
            float xs = (u == 0) ? xv.x : (u == 1) ? xv.y : (u == 2) ? xv.z : xv.w;
            unsigned long long xs2 = pack2(xs);
            const int base = (kk * 4 + u) * DFEAT + hoff;
            #pragma unroll
            for (int jq = 0; jq < 8; jq++) {
                ulonglong2 w = ldW2x2<L>(base + jq * 4);   // one LDC.128 = 4 cols
                ffma2(a[jq * 2 + 0], w.x, xs2);
                ffma2(a[jq * 2 + 1], w.y, xs2);
            }
        }
    }

    float dr = g_dis[row];
    // unpack + scale + pack 32 cols -> 32 halves = 4 x uint4 stores
    uint4* ho = reinterpret_cast<uint4*>(hs + (size_t)row * DFEAT + hoff);
    #pragma unroll
    for (int q = 0; q < 4; q++) {
        __half2 p[4];
        #pragma unroll
        for (int i = 0; i < 4; i++) {
            float2 f = unpack2(a[q * 4 + i]);
            p[i] = __floats2half2_rn(f.x * dr, f.y * dr);
        }
        ho[q] = *reinterpret_cast<uint4*>(p);
    }
}

// Gather-aggregate + finalize: 8 threads per node (one uint4 = 8 halves each).
//   s = hs[n] + sum_{k<cnt[n]} hs[slots[n][k]]   (fp32 accumulation)
//   o = relu(dis[n] * s + b)
// DO_READOUT: instead of writing o, accumulate dot(o, lin_w) into out[batch[n]].
template <bool DO_READOUT>
__global__ void aggregate_kernel(const __half* __restrict__ hs,
                                 const float*  __restrict__ b,
                                 float* __restrict__ xout,
                                 const int*   __restrict__ batch,
                                 const float* __restrict__ lin_w,
                                 float* __restrict__ out)
{
    __shared__ float bins[NGRAPH];
    if (DO_READOUT) {
        if (threadIdx.x < NGRAPH) bins[threadIdx.x] = 0.0f;
        __syncthreads();
    }

    int t = blockIdx.x * blockDim.x + threadIdx.x;
    int n = t >> 3;
    int c = t & 7;
    if (n < NNODES) {
        const uint4* hv = reinterpret_cast<const uint4*>(hs);   // 8 halves / uint4
        const int* sl = &g_slots[(size_t)n * SLOT];
        int cnt = g_cnt[n];

        float acc[8];
        {   // self loop
            uint4 r = __ldg(&hv[n * 8 + c]);
            const __half2* h = reinterpret_cast<const __half2*>(&r);
            #pragma unroll
            for (int i = 0; i < 4; i++) {
                float2 f = __half22float2(h[i]);
                acc[i * 2] = f.x; acc[i * 2 + 1] = f.y;
            }
        }
        int k = 0;
        for (; k + 1 < cnt; k += 2) {        // unroll-2 for MLP
            int s0 = __ldg(&sl[k]);
            int s1 = __ldg(&sl[k + 1]);
            uint4 r0 = __ldg(&hv[s0 * 8 + c]);
            uint4 r1 = __ldg(&hv[s1 * 8 + c]);
            const __half2* h0 = reinterpret_cast<const __half2*>(&r0);
            const __half2* h1 = reinterpret_cast<const __half2*>(&r1);
            #pragma unroll
            for (int i = 0; i < 4; i++) {
                float2 f0 = __half22float2(h0[i]);
                float2 f1 = __half22float2(h1[i]);
                acc[i * 2]     += f0.x + f1.x;
                acc[i * 2 + 1] += f0.y + f1.y;
            }
        }
        if (k < cnt) {
            int s0 = __ldg(&sl[k]);
            uint4 r0 = __ldg(&hv[s0 * 8 + c]);
            const __half2* h0 = reinterpret_cast<const __half2*>(&r0);
            #pragma unroll
            for (int i = 0; i < 4; i++) {
                float2 f0 = __half22float2(h0[i]);
                acc[i * 2] += f0.x; acc[i * 2 + 1] += f0.y;
            }
        }

        float dr = g_dis[n];
        const float4* bb = reinterpret_cast<const float4*>(&b[c * 8]);
        float4 b0 = __ldg(&bb[0]);
        float4 b1 = __ldg(&bb[1]);
        float o[8];
        o[0] = fmaxf(fmaf(dr, acc[0], b0.x), 0.0f);
        o[1] = fmaxf(fmaf(dr, acc[1], b0.y), 0.0f);
        o[2] = fmaxf(fmaf(dr, acc[2], b0.z), 0.0f);
        o[3] = fmaxf(fmaf(dr, acc[3], b0.w), 0.0f);
        o[4] = fmaxf(fmaf(dr, acc[4], b1.x), 0.0f);
        o[5] = fmaxf(fmaf(dr, acc[5], b1.y), 0.0f);
        o[6] = fmaxf(fmaf(dr, acc[6], b1.z), 0.0f);
        o[7] = fmaxf(fmaf(dr, acc[7], b1.w), 0.0f);

        if (!DO_READOUT) {
            float4* xo = reinterpret_cast<float4*>(xout + (size_t)n * DFEAT + c * 8);
            xo[0] = make_float4(o[0], o[1], o[2], o[3]);
            xo[1] = make_float4(o[4], o[5], o[6], o[7]);
        } else {
            const float4* lwv = reinterpret_cast<const float4*>(&lin_w[c * 8]);
            float4 l0 = __ldg(&lwv[0]);
            float4 l1 = __ldg(&lwv[1]);
            float d = o[0]*l0.x + o[1]*l0.y + o[2]*l0.z + o[3]*l0.w
                    + o[4]*l1.x + o[5]*l1.y + o[6]*l1.z + o[7]*l1.w;
            // reduce across the 8-lane group
            #pragma unroll
            for (int off = 4; off >= 1; off >>= 1)
                d += __shfl_down_sync(0xFFFFFFFFu, d, off, 8);
            if (c == 0) atomicAdd(&bins[__ldg(&batch[n])], d);
        }
    }

    if (DO_READOUT) {
        __syncthreads();
        if (threadIdx.x < NGRAPH && bins[threadIdx.x] != 0.0f)
            atomicAdd(&out[threadIdx.x], bins[threadIdx.x]);
    }
}

// ---------------- launch ----------------
extern "C" void kernel_launch(void* const* d_in, const int* in_sizes, int n_in,
                              void* d_out, int out_size)
{
    const float* x     = (const float*)d_in[0];
    const int*   eidx  = (const int*)  d_in[1];   // [2, E]: row 0 = src, row 1 = dst
    const int*   batch = (const int*)  d_in[2];
    const float* W1    = (const float*)d_in[3];
    const float* b1    = (const float*)d_in[4];
    const float* W2    = (const float*)d_in[5];
    const float* b2    = (const float*)d_in[6];
    const float* W3    = (const float*)d_in[7];
    const float* b3    = (const float*)d_in[8];
    const float* lin_w = (const float*)d_in[9];
    const float* lin_b = (const float*)d_in[10];
    float* out = (float*)d_out;

    const int* src = eidx;
    const int* dst = eidx + NEDGES;

    __half* hs;
    float *x1, *x2;
    cudaGetSymbolAddress((void**)&hs, g_hs);
    cudaGetSymbolAddress((void**)&x1, g_x1);
    cudaGetSymbolAddress((void**)&x2, g_x2);

    // Stage weights into constant memory (plain D2D async copies; allowed
    // under graph capture).
    void *pW1, *pW2, *pW3;
    cudaGetSymbolAddress(&pW1, cW1);
    cudaGetSymbolAddress(&pW2, cW2);
    cudaGetSymbolAddress(&pW3, cW3);
    cudaMemcpyAsync(pW1, W1, DFEAT * DFEAT * sizeof(float),
                    cudaMemcpyDeviceToDevice, 0);
    cudaMemcpyAsync(pW2, W2, DFEAT * DFEAT * sizeof(float),
                    cudaMemcpyDeviceToDevice, 0);
    cudaMemcpyAsync(pW3, W3, DFEAT * DFEAT * sizeof(float),
                    cudaMemcpyDeviceToDevice, 0);

    const int TB = 256;
    dim3 gN((NNODES + TB - 1) / TB);
    dim3 gE((NEDGES + TB - 1) / TB);
    dim3 gN8((NNODES * 8 + TB - 1) / TB);
    dim3 gG((NNODES + 255) / 256, 2);   // gemm: 256 rows/block, y = column half

    // degree buckets + norm
    init_kernel<<<gN, TB>>>(out, lin_b);
    build_kernel<<<gE, TB>>>(src, dst);
    dis_kernel<<<gN, TB>>>();

    // layer 1: x -> x1
    gemm_scale_kernel<0><<<gG, 256>>>(x, hs);
    aggregate_kernel<false><<<gN8, TB>>>(hs, b1, x1, nullptr, nullptr, nullptr);
    // layer 2: x1 -> x2
    gemm_scale_kernel<1><<<gG, 256>>>(x1, hs);
    aggregate_kernel<false><<<gN8, TB>>>(hs, b2, x2, nullptr, nullptr, nullptr);
    // layer 3: x2 -> (fused pool + linear head)
    gemm_scale_kernel<2><<<gG, 256>>>(x2, hs);
    aggregate_kernel<true><<<gN8, TB>>>(hs, b3, nullptr, batch, lin_w, out);
}